// round 2
// baseline (speedup 1.0000x reference)
#include <cuda_runtime.h>

#define T_SEQ   2048
#define BATCH   64
#define INP     16
#define HEADS   8
#define HID     64
#define GATES   256      // 4*HID
#define BC      4        // batches per CTA
#define NTHREADS 256
#define OUT_ELEMS  (T_SEQ * BATCH * HEADS)
#define LOUT_ELEMS (T_SEQ * BATCH * HID)

// Packed fp32x2 FMA (sm_100+): 2 MACs per instruction, 2x FFMA throughput.
__device__ __forceinline__ float2 ffma2(float2 a, float2 b, float2 c) {
    float2 d;
    asm("fma.rn.f32x2 %0, %1, %2, %3;"
        : "=l"(reinterpret_cast<unsigned long long&>(d))
        : "l"(reinterpret_cast<const unsigned long long&>(a)),
          "l"(reinterpret_cast<const unsigned long long&>(b)),
          "l"(reinterpret_cast<const unsigned long long&>(c)));
    return d;
}

// Fast but accurate-enough gates: EX2-based exp (~2 ulp) + approx division
// (~2^-21 rel). Large-|x| saturation behaves correctly (inf -> 0/1).
__device__ __forceinline__ float fsig(float x) {
    return __fdividef(1.0f, 1.0f + __expf(-x));
}
__device__ __forceinline__ float ftanh_(float x) {
    return fmaf(2.0f, fsig(2.0f * x), -1.0f);
}

__global__ void __launch_bounds__(NTHREADS)
lstm_kernel(const float* __restrict__ x,    const float* __restrict__ Wih,
            const float* __restrict__ Whh,  const float* __restrict__ bih,
            const float* __restrict__ bhh,  const float* __restrict__ Wlin,
            const float* __restrict__ blin, float* __restrict__ out,
            float* __restrict__ lout)
{
    const int h  = blockIdx.x >> 4;           // head 0..7
    const int b0 = (blockIdx.x & 15) * BC;    // first batch of this CTA
    const int j  = threadIdx.x;               // gate row 0..255
    const int d  = j & (HID - 1);             // hidden index (phase 2)
    const int bb = j >> 6;                    // batch-within-chunk (phase 2)

    __shared__ __align__(16) float hs[BC * HID];        // h_{t-1} [bb][d]
    __shared__ __align__(16) float zb[GATES * BC];      // z [j][bb]
    __shared__ __align__(16) float xs[2 * BC * INP];    // x double buffer
    __shared__ float red[8];                            // per-warp partials

    // ---- weights -> registers (row j of W_hh[h], W_ih[h]) ----
    float2 w2[HID / 2];
    {
        const float4* wr = reinterpret_cast<const float4*>(Whh + (size_t)(h * GATES + j) * HID);
#pragma unroll
        for (int q = 0; q < HID / 4; ++q) {
            float4 v = wr[q];
            w2[2 * q]     = make_float2(v.x, v.y);
            w2[2 * q + 1] = make_float2(v.z, v.w);
        }
    }
    float2 wi2[INP / 2];
    {
        const float4* wr = reinterpret_cast<const float4*>(Wih + (size_t)(h * GATES + j) * INP);
#pragma unroll
        for (int q = 0; q < INP / 4; ++q) {
            float4 v = wr[q];
            wi2[2 * q]     = make_float2(v.x, v.y);
            wi2[2 * q + 1] = make_float2(v.z, v.w);
        }
    }
    const float bias   = bih[h * GATES + j] + bhh[h * GATES + j];
    const float wlin_d = Wlin[h * HID + d];
    const float blin_v = blin[h];

    // ---- init ----
    hs[j] = 0.0f;                 // BC*HID == 256 == NTHREADS
    float c = 0.0f;
    float xreg = 0.0f;
    if (j < BC * INP) {
        xs[j]   = x[(size_t)0 * BATCH * INP + b0 * INP + j];   // t=0
        xreg    = x[(size_t)1 * BATCH * INP + b0 * INP + j];   // prefetch t=1
    }
    __syncthreads();

    for (int t = 0; t < T_SEQ; ++t) {
        // deferred store of out[t-1] (red written last phase-2, visible now)
        if (j < BC && t > 0) {
            out[(size_t)((t - 1) * BATCH + b0 + j) * HEADS + h] =
                red[2 * j] + red[2 * j + 1] + blin_v;
        }

        // ---- phase 1: z_j[b] = bias + Whh_row_j . h[b] + Wih_row_j . x_t[b] ----
        const float* xbuf = xs + (t & 1) * (BC * INP);
        float4 zout;
        float* zp = &zout.x;
#pragma unroll
        for (int b = 0; b < BC; ++b) {
            float2 a0 = make_float2(bias, 0.0f);
            float2 a1 = make_float2(0.0f, 0.0f);
            const float4* hv = reinterpret_cast<const float4*>(hs + b * HID);
#pragma unroll
            for (int q = 0; q < HID / 4; ++q) {
                float4 v = hv[q];
                a0 = ffma2(w2[2 * q],     make_float2(v.x, v.y), a0);
                a1 = ffma2(w2[2 * q + 1], make_float2(v.z, v.w), a1);
            }
            const float4* xv = reinterpret_cast<const float4*>(xbuf + b * INP);
#pragma unroll
            for (int q = 0; q < INP / 4; ++q) {
                float4 v = xv[q];
                a0 = ffma2(wi2[2 * q],     make_float2(v.x, v.y), a0);
                a1 = ffma2(wi2[2 * q + 1], make_float2(v.z, v.w), a1);
            }
            zp[b] = (a0.x + a0.y) + (a1.x + a1.y);
        }
        *reinterpret_cast<float4*>(zb + j * 4) = zout;
        __syncthreads();

        // ---- phase 2: gates, state update, outputs (thread = (bb, d)) ----
        float zi = zb[(0 * HID + d) * BC + bb];
        float zf = zb[(1 * HID + d) * BC + bb];
        float zg = zb[(2 * HID + d) * BC + bb];
        float zo = zb[(3 * HID + d) * BC + bb];
        float ig = fsig(zi) * ftanh_(zg);
        c = fmaf(fsig(zf), c, ig);
        float hval = fsig(zo) * ftanh_(c);
        hs[bb * HID + d] = hval;

        // lstm_output head-sum: fire-and-forget RED to distinct addresses
        atomicAdd(lout + (size_t)(t * BATCH + b0 + bb) * HID + d, hval);

        // per-head linear: reduce h . W_lin over d (64 threads = 2 warps)
        float p = hval * wlin_d;
#pragma unroll
        for (int s = 16; s; s >>= 1) p += __shfl_down_sync(0xffffffffu, p, s);
        if ((j & 31) == 0) red[j >> 5] = p;

        // x pipeline: publish x_{t+1} (loaded a full step ago), prefetch x_{t+2}
        if (j < BC * INP) {
            if (t + 1 < T_SEQ) xs[((t + 1) & 1) * (BC * INP) + j] = xreg;
            if (t + 2 < T_SEQ) xreg = x[(size_t)(t + 2) * BATCH * INP + b0 * INP + j];
        }
        __syncthreads();
    }

    // final out row (t = T-1)
    if (j < BC) {
        out[(size_t)((T_SEQ - 1) * BATCH + b0 + j) * HEADS + h] =
            red[2 * j] + red[2 * j + 1] + blin_v;
    }
}

extern "C" void kernel_launch(void* const* d_in, const int* in_sizes, int n_in,
                              void* d_out, int out_size) {
    const float* x    = (const float*)d_in[0];
    const float* Wih  = (const float*)d_in[1];
    const float* Whh  = (const float*)d_in[2];
    const float* bih  = (const float*)d_in[3];
    const float* bhh  = (const float*)d_in[4];
    const float* Wlin = (const float*)d_in[5];
    const float* blin = (const float*)d_in[6];

    float* out  = (float*)d_out;                 // (T,B,H)
    float* lout = out + OUT_ELEMS;               // (T,B,HID), accumulated

    // lstm_output region is accumulated with atomics -> must start at zero.
    cudaMemsetAsync(lout, 0, (size_t)LOUT_ELEMS * sizeof(float), 0);

    lstm_kernel<<<HEADS * (BATCH / BC), NTHREADS>>>(
        x, Wih, Whh, bih, bhh, Wlin, blin, out, lout);
}